// round 1
// baseline (speedup 1.0000x reference)
#include <cuda_runtime.h>
#include <math.h>

// ---------------------------------------------------------------------------
// Swin Transformer block, fp32 baseline.
// B=32, H=W=56, C=192, WS=7, SS=3, NH=6, hd=32. Tokens T = 100352.
// Pipeline:
//   1. ln_stats(x)                 -> mu1, rs1
//   2. gemm_qkv  (LN + roll/window perm fused into A-load)   -> g_qkv
//   3. attn_kernel (per window*head, bias+mask in-kernel)    -> g_att
//   4. gemm_proj (un-window/un-roll + residual in epilogue)  -> d_out (= y)
//   5. ln_stats(y)                 -> mu2, rs2
//   6. gemm_fc1  (LN fused, GELU epilogue)                   -> g_h
//   7. gemm_fc2  (in-place residual epilogue)                -> d_out (final)
// ---------------------------------------------------------------------------

#define TOKENS 100352           // 32*56*56
#define HDIM   56
#define CDIM   192

// Scratch (allocation-free rule: __device__ globals)
__device__ float g_qkv[(size_t)TOKENS * 576];   // 231 MB
__device__ float g_att[(size_t)TOKENS * 192];   //  77 MB
__device__ float g_h  [(size_t)TOKENS * 768];   // 308 MB
__device__ float g_mu1[TOKENS], g_rs1[TOKENS];
__device__ float g_mu2[TOKENS], g_rs2[TOKENS];

// Window-order token t -> original pixel index (handles roll(-3,-3),
// window partition, and equivalently the inverse un-window + roll(+3,+3)).
__device__ __forceinline__ int perm_pixel(int t) {
    int b  = t / 3136;            // 64 windows * 49 tokens
    int r  = t - b * 3136;
    int wi = r / 49;
    int n  = r - wi * 49;
    int wh = wi >> 3, ww = wi & 7;
    int i  = n / 7,   j  = n - i * 7;
    int h  = wh * 7 + i + 3; if (h >= HDIM) h -= HDIM;
    int w  = ww * 7 + j + 3; if (w >= HDIM) w -= HDIM;
    return (b * HDIM + h) * HDIM + w;
}

// ---------------------------------------------------------------------------
// LayerNorm statistics: one warp per token, 192 elements.
// which==0 -> (g_mu1,g_rs1), which==1 -> (g_mu2,g_rs2)
// ---------------------------------------------------------------------------
__global__ __launch_bounds__(256) void ln_stats(const float* __restrict__ x, int which) {
    int t = blockIdx.x * 8 + (threadIdx.x >> 5);
    int lane = threadIdx.x & 31;
    if (t >= TOKENS) return;
    const float* row = x + (size_t)t * CDIM;
    float s = 0.f, s2 = 0.f;
    #pragma unroll
    for (int i = 0; i < 6; i++) {
        float v = row[lane + 32 * i];
        s += v; s2 += v * v;
    }
    #pragma unroll
    for (int o = 16; o; o >>= 1) {
        s  += __shfl_xor_sync(0xFFFFFFFFu, s,  o);
        s2 += __shfl_xor_sync(0xFFFFFFFFu, s2, o);
    }
    if (lane == 0) {
        float m   = s * (1.f / 192.f);
        float var = s2 * (1.f / 192.f) - m * m;
        float rs  = rsqrtf(var + 1e-5f);
        if (which == 0) { g_mu1[t] = m; g_rs1[t] = rs; }
        else            { g_mu2[t] = m; g_rs2[t] = rs; }
    }
}

// ---------------------------------------------------------------------------
// GEMM tile config: BM=64, BN=64, BK=32, 256 threads, 4x4 microtile.
// ---------------------------------------------------------------------------

// QKV: out[t, n] = LN(x[perm(t)]) @ qkv_w + qkv_b    (K=192, N=576)
__global__ __launch_bounds__(256) void gemm_qkv(
    const float* __restrict__ x, const float* __restrict__ w,
    const float* __restrict__ wb, const float* __restrict__ g,
    const float* __restrict__ bb)
{
    __shared__ float As[64][36];
    __shared__ float Bs[32][64];
    __shared__ int   rP[64];
    __shared__ float rM[64], rR[64];
    int tid = threadIdx.x;
    int tx = tid & 15, ty = tid >> 4;
    int m0 = blockIdx.x << 6;
    int n0 = blockIdx.y << 6;
    if (tid < 64) {
        int p = perm_pixel(m0 + tid);
        rP[tid] = p; rM[tid] = g_mu1[p]; rR[tid] = g_rs1[p];
    }
    __syncthreads();
    float acc[4][4] = {};
    for (int kt = 0; kt < 192; kt += 32) {
        #pragma unroll
        for (int e = 0; e < 2; e++) {
            int idx = tid + e * 256;
            int r = idx >> 3, c = (idx & 7) << 2;
            int gk = kt + c;
            float4 xv = *(const float4*)(x + (size_t)rP[r] * CDIM + gk);
            float4 gv = *(const float4*)(g + gk);
            float4 bv = *(const float4*)(bb + gk);
            float mm = rM[r], rr = rR[r];
            As[r][c + 0] = (xv.x - mm) * rr * gv.x + bv.x;
            As[r][c + 1] = (xv.y - mm) * rr * gv.y + bv.y;
            As[r][c + 2] = (xv.z - mm) * rr * gv.z + bv.z;
            As[r][c + 3] = (xv.w - mm) * rr * gv.w + bv.w;
        }
        #pragma unroll
        for (int e = 0; e < 2; e++) {
            int idx = tid + e * 256;
            int r = idx >> 4, c = (idx & 15) << 2;
            *(float4*)&Bs[r][c] = *(const float4*)(w + (size_t)(kt + r) * 576 + n0 + c);
        }
        __syncthreads();
        #pragma unroll
        for (int k = 0; k < 32; k++) {
            float4 b4 = *(float4*)&Bs[k][tx << 2];
            #pragma unroll
            for (int i = 0; i < 4; i++) {
                float a = As[(ty << 2) + i][k];
                acc[i][0] += a * b4.x; acc[i][1] += a * b4.y;
                acc[i][2] += a * b4.z; acc[i][3] += a * b4.w;
            }
        }
        __syncthreads();
    }
    float4 bias = *(const float4*)(wb + n0 + (tx << 2));
    #pragma unroll
    for (int i = 0; i < 4; i++) {
        int t = m0 + (ty << 2) + i;
        float4 o;
        o.x = acc[i][0] + bias.x; o.y = acc[i][1] + bias.y;
        o.z = acc[i][2] + bias.z; o.w = acc[i][3] + bias.w;
        *(float4*)(g_qkv + (size_t)t * 576 + n0 + (tx << 2)) = o;
    }
}

// ---------------------------------------------------------------------------
// Attention: one block per (batch*window, head). 12288 blocks, 128 threads.
// ---------------------------------------------------------------------------
__global__ __launch_bounds__(128) void attn_kernel(const float* __restrict__ rpb) {
    __shared__ float sq[49][33], sk[49][33], sv[49][33];
    __shared__ float sp[49][56];
    int head = blockIdx.x % 6;
    int wg   = blockIdx.x / 6;            // b*64 + wi
    int wi   = wg & 63;
    int wh   = wi >> 3, ww = wi & 7;
    int tid  = threadIdx.x;

    size_t base = (size_t)wg * 49 * 576 + head * 32;
    for (int idx = tid; idx < 49 * 32; idx += 128) {
        int n = idx >> 5, d = idx & 31;
        size_t o = base + (size_t)n * 576 + d;
        sq[n][d] = g_qkv[o];
        sk[n][d] = g_qkv[o + 192];
        sv[n][d] = g_qkv[o + 384];
    }
    __syncthreads();

    const float scale = 0.17677669529663687f;   // 1/sqrt(32)
    bool edge_h = (wh == 7), edge_w = (ww == 7);
    for (int idx = tid; idx < 49 * 49; idx += 128) {
        int n = idx / 49, m = idx - n * 49;
        float s = 0.f;
        #pragma unroll
        for (int d = 0; d < 32; d++) s += sq[n][d] * sk[m][d];
        int i1 = n / 7, j1 = n - i1 * 7;
        int i2 = m / 7, j2 = m - i2 * 7;
        float bias = rpb[((i1 - i2 + 6) * 13 + (j1 - j2 + 6)) * 6 + head];
        int rn = (edge_h ? ((i1 < 4) ? 1 : 2) : 0) * 3 + (edge_w ? ((j1 < 4) ? 1 : 2) : 0);
        int rm = (edge_h ? ((i2 < 4) ? 1 : 2) : 0) * 3 + (edge_w ? ((j2 < 4) ? 1 : 2) : 0);
        if (rn != rm) bias -= 100.f;
        sp[n][m] = s * scale + bias;
    }
    __syncthreads();

    if (tid < 49) {
        float mx = -1e30f;
        #pragma unroll 7
        for (int m = 0; m < 49; m++) mx = fmaxf(mx, sp[tid][m]);
        float sum = 0.f;
        #pragma unroll 7
        for (int m = 0; m < 49; m++) { float e = expf(sp[tid][m] - mx); sp[tid][m] = e; sum += e; }
        float inv = 1.f / sum;
        #pragma unroll 7
        for (int m = 0; m < 49; m++) sp[tid][m] *= inv;
    }
    __syncthreads();

    for (int idx = tid; idx < 49 * 32; idx += 128) {
        int n = idx >> 5, d = idx & 31;
        float s = 0.f;
        #pragma unroll 7
        for (int m = 0; m < 49; m++) s += sp[n][m] * sv[m][d];
        g_att[(size_t)(wg * 49 + n) * CDIM + head * 32 + d] = s;
    }
}

// ---------------------------------------------------------------------------
// Proj: y[perm(t)] = x[perm(t)] + g_att[t] @ proj_w + proj_b   (K=192, N=192)
// ---------------------------------------------------------------------------
__global__ __launch_bounds__(256) void gemm_proj(
    const float* __restrict__ x, const float* __restrict__ w,
    const float* __restrict__ wb, float* __restrict__ out)
{
    __shared__ float As[64][36];
    __shared__ float Bs[32][64];
    int tid = threadIdx.x;
    int tx = tid & 15, ty = tid >> 4;
    int m0 = blockIdx.x << 6;
    int n0 = blockIdx.y << 6;
    float acc[4][4] = {};
    for (int kt = 0; kt < 192; kt += 32) {
        #pragma unroll
        for (int e = 0; e < 2; e++) {
            int idx = tid + e * 256;
            int r = idx >> 3, c = (idx & 7) << 2;
            *(float4*)&As[r][c] = *(const float4*)(g_att + (size_t)(m0 + r) * CDIM + kt + c);
        }
        #pragma unroll
        for (int e = 0; e < 2; e++) {
            int idx = tid + e * 256;
            int r = idx >> 4, c = (idx & 15) << 2;
            *(float4*)&Bs[r][c] = *(const float4*)(w + (size_t)(kt + r) * CDIM + n0 + c);
        }
        __syncthreads();
        #pragma unroll
        for (int k = 0; k < 32; k++) {
            float4 b4 = *(float4*)&Bs[k][tx << 2];
            #pragma unroll
            for (int i = 0; i < 4; i++) {
                float a = As[(ty << 2) + i][k];
                acc[i][0] += a * b4.x; acc[i][1] += a * b4.y;
                acc[i][2] += a * b4.z; acc[i][3] += a * b4.w;
            }
        }
        __syncthreads();
    }
    float4 bias = *(const float4*)(wb + n0 + (tx << 2));
    #pragma unroll
    for (int i = 0; i < 4; i++) {
        int t = m0 + (ty << 2) + i;
        int p = perm_pixel(t);
        float4 sc = *(const float4*)(x + (size_t)p * CDIM + n0 + (tx << 2));
        float4 o;
        o.x = acc[i][0] + bias.x + sc.x; o.y = acc[i][1] + bias.y + sc.y;
        o.z = acc[i][2] + bias.z + sc.z; o.w = acc[i][3] + bias.w + sc.w;
        *(float4*)(out + (size_t)p * CDIM + n0 + (tx << 2)) = o;
    }
}

// ---------------------------------------------------------------------------
// FC1: g_h[t] = gelu( LN2(y[t]) @ fc1_w + fc1_b )   (K=192, N=768)
// ---------------------------------------------------------------------------
__global__ __launch_bounds__(256) void gemm_fc1(
    const float* __restrict__ y, const float* __restrict__ w,
    const float* __restrict__ wb, const float* __restrict__ g,
    const float* __restrict__ bb)
{
    __shared__ float As[64][36];
    __shared__ float Bs[32][64];
    __shared__ float rM[64], rR[64];
    int tid = threadIdx.x;
    int tx = tid & 15, ty = tid >> 4;
    int m0 = blockIdx.x << 6;
    int n0 = blockIdx.y << 6;
    if (tid < 64) { rM[tid] = g_mu2[m0 + tid]; rR[tid] = g_rs2[m0 + tid]; }
    __syncthreads();
    float acc[4][4] = {};
    for (int kt = 0; kt < 192; kt += 32) {
        #pragma unroll
        for (int e = 0; e < 2; e++) {
            int idx = tid + e * 256;
            int r = idx >> 3, c = (idx & 7) << 2;
            int gk = kt + c;
            float4 xv = *(const float4*)(y + (size_t)(m0 + r) * CDIM + gk);
            float4 gv = *(const float4*)(g + gk);
            float4 bv = *(const float4*)(bb + gk);
            float mm = rM[r], rr = rR[r];
            As[r][c + 0] = (xv.x - mm) * rr * gv.x + bv.x;
            As[r][c + 1] = (xv.y - mm) * rr * gv.y + bv.y;
            As[r][c + 2] = (xv.z - mm) * rr * gv.z + bv.z;
            As[r][c + 3] = (xv.w - mm) * rr * gv.w + bv.w;
        }
        #pragma unroll
        for (int e = 0; e < 2; e++) {
            int idx = tid + e * 256;
            int r = idx >> 4, c = (idx & 15) << 2;
            *(float4*)&Bs[r][c] = *(const float4*)(w + (size_t)(kt + r) * 768 + n0 + c);
        }
        __syncthreads();
        #pragma unroll
        for (int k = 0; k < 32; k++) {
            float4 b4 = *(float4*)&Bs[k][tx << 2];
            #pragma unroll
            for (int i = 0; i < 4; i++) {
                float a = As[(ty << 2) + i][k];
                acc[i][0] += a * b4.x; acc[i][1] += a * b4.y;
                acc[i][2] += a * b4.z; acc[i][3] += a * b4.w;
            }
        }
        __syncthreads();
    }
    float4 bias = *(const float4*)(wb + n0 + (tx << 2));
    #pragma unroll
    for (int i = 0; i < 4; i++) {
        int t = m0 + (ty << 2) + i;
        float v[4] = { acc[i][0] + bias.x, acc[i][1] + bias.y,
                       acc[i][2] + bias.z, acc[i][3] + bias.w };
        float4 o;
        o.x = 0.5f * v[0] * (1.f + erff(v[0] * 0.70710678118654752f));
        o.y = 0.5f * v[1] * (1.f + erff(v[1] * 0.70710678118654752f));
        o.z = 0.5f * v[2] * (1.f + erff(v[2] * 0.70710678118654752f));
        o.w = 0.5f * v[3] * (1.f + erff(v[3] * 0.70710678118654752f));
        *(float4*)(g_h + (size_t)t * 768 + n0 + (tx << 2)) = o;
    }
}

// ---------------------------------------------------------------------------
// FC2: out[t] = y[t] + g_h[t] @ fc2_w + fc2_b   (K=768, N=192), in-place on out
// ---------------------------------------------------------------------------
__global__ __launch_bounds__(256) void gemm_fc2(
    const float* __restrict__ w, const float* __restrict__ wb,
    float* __restrict__ out)
{
    __shared__ float As[64][36];
    __shared__ float Bs[32][64];
    int tid = threadIdx.x;
    int tx = tid & 15, ty = tid >> 4;
    int m0 = blockIdx.x << 6;
    int n0 = blockIdx.y << 6;
    float acc[4][4] = {};
    for (int kt = 0; kt < 768; kt += 32) {
        #pragma unroll
        for (int e = 0; e < 2; e++) {
            int idx = tid + e * 256;
            int r = idx >> 3, c = (idx & 7) << 2;
            *(float4*)&As[r][c] = *(const float4*)(g_h + (size_t)(m0 + r) * 768 + kt + c);
        }
        #pragma unroll
        for (int e = 0; e < 2; e++) {
            int idx = tid + e * 256;
            int r = idx >> 4, c = (idx & 15) << 2;
            *(float4*)&Bs[r][c] = *(const float4*)(w + (size_t)(kt + r) * CDIM + n0 + c);
        }
        __syncthreads();
        #pragma unroll
        for (int k = 0; k < 32; k++) {
            float4 b4 = *(float4*)&Bs[k][tx << 2];
            #pragma unroll
            for (int i = 0; i < 4; i++) {
                float a = As[(ty << 2) + i][k];
                acc[i][0] += a * b4.x; acc[i][1] += a * b4.y;
                acc[i][2] += a * b4.z; acc[i][3] += a * b4.w;
            }
        }
        __syncthreads();
    }
    float4 bias = *(const float4*)(wb + n0 + (tx << 2));
    #pragma unroll
    for (int i = 0; i < 4; i++) {
        int t = m0 + (ty << 2) + i;
        float4 yv = *(const float4*)(out + (size_t)t * CDIM + n0 + (tx << 2));
        float4 o;
        o.x = yv.x + acc[i][0] + bias.x; o.y = yv.y + acc[i][1] + bias.y;
        o.z = yv.z + acc[i][2] + bias.z; o.w = yv.w + acc[i][3] + bias.w;
        *(float4*)(out + (size_t)t * CDIM + n0 + (tx << 2)) = o;
    }
}

// ---------------------------------------------------------------------------
extern "C" void kernel_launch(void* const* d_in, const int* in_sizes, int n_in,
                              void* d_out, int out_size) {
    const float* x      = (const float*)d_in[0];
    const float* n1g    = (const float*)d_in[1];
    const float* n1b    = (const float*)d_in[2];
    const float* qkv_w  = (const float*)d_in[3];
    const float* qkv_b  = (const float*)d_in[4];
    const float* rpb    = (const float*)d_in[5];
    const float* proj_w = (const float*)d_in[6];
    const float* proj_b = (const float*)d_in[7];
    const float* n2g    = (const float*)d_in[8];
    const float* n2b    = (const float*)d_in[9];
    const float* fc1_w  = (const float*)d_in[10];
    const float* fc1_b  = (const float*)d_in[11];
    const float* fc2_w  = (const float*)d_in[12];
    const float* fc2_b  = (const float*)d_in[13];
    float* out = (float*)d_out;

    ln_stats<<<TOKENS / 8, 256>>>(x, 0);
    gemm_qkv<<<dim3(1568, 9), 256>>>(x, qkv_w, qkv_b, n1g, n1b);
    attn_kernel<<<12288, 128>>>(rpb);
    gemm_proj<<<dim3(1568, 3), 256>>>(x, proj_w, proj_b, out);
    ln_stats<<<TOKENS / 8, 256>>>(out, 1);
    gemm_fc1<<<dim3(1568, 12), 256>>>(out, fc1_w, fc1_b, n2g, n2b);
    gemm_fc2<<<dim3(1568, 3), 256>>>(fc2_w, fc2_b, out);
}

// round 2
// speedup vs baseline: 1.8611x; 1.8611x over previous
#include <cuda_runtime.h>
#include <math.h>

// ---------------------------------------------------------------------------
// Swin Transformer block — TF32 tensor-core version.
// B=32, H=W=56, C=192, WS=7, SS=3, NH=6, hd=32. Tokens T = 100352.
//   1. ln_stats(x)                 -> mu1, rs1
//   2. gemm_qkv_t  (LN+perm fused, tf32 mma)   -> g_qkv
//   3. attn_t      (QK^T + softmax + PV, tf32 mma per window*head) -> g_att
//   4. gemm_proj_t (un-perm + residual)        -> d_out (= y)
//   5. ln_stats(y)                 -> mu2, rs2
//   6. gemm_fc1_t  (LN fused, GELU epilogue)   -> g_h
//   7. gemm_fc2_t  (in-place residual)         -> d_out
// ---------------------------------------------------------------------------

#define TOKENS 100352
#define HDIM   56
#define CDIM   192

__device__ float g_qkv[(size_t)TOKENS * 576];
__device__ float g_att[(size_t)TOKENS * 192];
__device__ float g_h  [(size_t)TOKENS * 768];
__device__ float g_mu1[TOKENS], g_rs1[TOKENS];
__device__ float g_mu2[TOKENS], g_rs2[TOKENS];

__device__ __forceinline__ unsigned f2tf(float f) {
    unsigned r;
    asm("cvt.rna.tf32.f32 %0, %1;" : "=r"(r) : "f"(f));
    return r;
}

__device__ __forceinline__ void mma8(float* d, const unsigned* a, const unsigned* b) {
    asm volatile(
        "mma.sync.aligned.m16n8k8.row.col.f32.tf32.tf32.f32 "
        "{%0,%1,%2,%3},{%4,%5,%6,%7},{%8,%9},{%0,%1,%2,%3};"
        : "+f"(d[0]), "+f"(d[1]), "+f"(d[2]), "+f"(d[3])
        : "r"(a[0]), "r"(a[1]), "r"(a[2]), "r"(a[3]), "r"(b[0]), "r"(b[1]));
}

__device__ __forceinline__ int perm_pixel(int t) {
    int b  = t / 3136;
    int r  = t - b * 3136;
    int wi = r / 49;
    int n  = r - wi * 49;
    int wh = wi >> 3, ww = wi & 7;
    int i  = n / 7,   j  = n - i * 7;
    int h  = wh * 7 + i + 3; if (h >= HDIM) h -= HDIM;
    int w  = ww * 7 + j + 3; if (w >= HDIM) w -= HDIM;
    return (b * HDIM + h) * HDIM + w;
}

// ---------------------------------------------------------------------------
__global__ __launch_bounds__(256) void ln_stats(const float* __restrict__ x, int which) {
    int t = blockIdx.x * 8 + (threadIdx.x >> 5);
    int lane = threadIdx.x & 31;
    if (t >= TOKENS) return;
    const float* row = x + (size_t)t * CDIM;
    float s = 0.f, s2 = 0.f;
    #pragma unroll
    for (int i = 0; i < 6; i++) {
        float v = row[lane + 32 * i];
        s += v; s2 += v * v;
    }
    #pragma unroll
    for (int o = 16; o; o >>= 1) {
        s  += __shfl_xor_sync(0xFFFFFFFFu, s,  o);
        s2 += __shfl_xor_sync(0xFFFFFFFFu, s2, o);
    }
    if (lane == 0) {
        float m   = s * (1.f / 192.f);
        float var = s2 * (1.f / 192.f) - m * m;
        float rs  = rsqrtf(var + 1e-5f);
        if (which == 0) { g_mu1[t] = m; g_rs1[t] = rs; }
        else            { g_mu2[t] = m; g_rs2[t] = rs; }
    }
}

// ---------------------------------------------------------------------------
// Shared mainloop piece: one BK=32 slab of mma for BM=128 x BN=64 tile.
// 8 warps: warp (wid>>1) owns m-rows [32*(wid>>1),+32), (wid&1) owns n [32*(wid&1),+32).
// ---------------------------------------------------------------------------
__device__ __forceinline__ void mma_tile(
    const unsigned (*As)[36], const unsigned (*Bs)[72],
    float d[2][4][4], int wm, int wn, int g, int t)
{
    #pragma unroll
    for (int ks = 0; ks < 4; ks++) {
        unsigned a[2][4], b[4][2];
        #pragma unroll
        for (int mi = 0; mi < 2; mi++) {
            int r = wm + mi * 16 + g;
            int c = ks * 8 + t;
            a[mi][0] = As[r][c];     a[mi][1] = As[r + 8][c];
            a[mi][2] = As[r][c + 4]; a[mi][3] = As[r + 8][c + 4];
        }
        #pragma unroll
        for (int ni = 0; ni < 4; ni++) {
            int c = wn + ni * 8 + g;
            b[ni][0] = Bs[ks * 8 + t][c];
            b[ni][1] = Bs[ks * 8 + t + 4][c];
        }
        #pragma unroll
        for (int mi = 0; mi < 2; mi++)
            #pragma unroll
            for (int ni = 0; ni < 4; ni++)
                mma8(d[mi][ni], a[mi], b[ni]);
    }
}

// ---------------------------------------------------------------------------
// QKV: g_qkv[t] = LN1(x[perm(t)]) @ qkv_w + qkv_b   (M=T, N=576, K=192)
// ---------------------------------------------------------------------------
__global__ __launch_bounds__(256) void gemm_qkv_t(
    const float* __restrict__ x, const float* __restrict__ w,
    const float* __restrict__ wb, const float* __restrict__ gg,
    const float* __restrict__ bb)
{
    __shared__ unsigned As[128][36];
    __shared__ unsigned Bs[32][72];
    __shared__ int   rP[128];
    __shared__ float rM[128], rR[128];
    int tid = threadIdx.x;
    int lane = tid & 31, wid = tid >> 5;
    int g = lane >> 2, t = lane & 3;
    int wm = (wid >> 1) * 32, wn = (wid & 1) * 32;
    int m0 = blockIdx.x << 7, n0 = blockIdx.y << 6;
    if (tid < 128) {
        int p = perm_pixel(m0 + tid);
        rP[tid] = p; rM[tid] = g_mu1[p]; rR[tid] = g_rs1[p];
    }
    __syncthreads();
    float d[2][4][4] = {};
    for (int kt = 0; kt < 192; kt += 32) {
        #pragma unroll
        for (int e = 0; e < 4; e++) {
            int idx = tid + e * 256;
            int r = idx >> 3, c = (idx & 7) << 2;
            int gk = kt + c;
            float4 xv = *(const float4*)(x + (size_t)rP[r] * CDIM + gk);
            float4 gv = *(const float4*)(gg + gk);
            float4 bv = *(const float4*)(bb + gk);
            float mm = rM[r], rr = rR[r];
            uint4 u;
            u.x = f2tf((xv.x - mm) * rr * gv.x + bv.x);
            u.y = f2tf((xv.y - mm) * rr * gv.y + bv.y);
            u.z = f2tf((xv.z - mm) * rr * gv.z + bv.z);
            u.w = f2tf((xv.w - mm) * rr * gv.w + bv.w);
            *(uint4*)&As[r][c] = u;
        }
        #pragma unroll
        for (int e = 0; e < 2; e++) {
            int idx = tid + e * 256;
            int r = idx >> 4, c = (idx & 15) << 2;
            float4 wv = *(const float4*)(w + (size_t)(kt + r) * 576 + n0 + c);
            uint4 u = { f2tf(wv.x), f2tf(wv.y), f2tf(wv.z), f2tf(wv.w) };
            *(uint4*)&Bs[r][c] = u;
        }
        __syncthreads();
        mma_tile(As, Bs, d, wm, wn, g, t);
        __syncthreads();
    }
    #pragma unroll
    for (int mi = 0; mi < 2; mi++)
        #pragma unroll
        for (int ni = 0; ni < 4; ni++) {
            int row = m0 + wm + mi * 16 + g;
            int col = n0 + wn + ni * 8 + 2 * t;
            float2 b2 = *(const float2*)(wb + col);
            float2 o0 = { d[mi][ni][0] + b2.x, d[mi][ni][1] + b2.y };
            float2 o1 = { d[mi][ni][2] + b2.x, d[mi][ni][3] + b2.y };
            *(float2*)(g_qkv + (size_t)row * 576 + col) = o0;
            *(float2*)(g_qkv + (size_t)(row + 8) * 576 + col) = o1;
        }
}

// ---------------------------------------------------------------------------
// Attention: one block per (batch*window, head). tf32 mma for QK^T and PV.
// ---------------------------------------------------------------------------
__global__ __launch_bounds__(128) void attn_t(const float* __restrict__ rpb) {
    __shared__ unsigned sq[64][36];   // Q, rows padded w/ zeros 49..63
    __shared__ unsigned sk[56][36];   // K, rows 49..55 zero
    __shared__ unsigned sv[56][40];   // V, rows 49..55 zero
    __shared__ float    sp[64][60];   // scores -> probs (tf32 bits as float)

    int head = blockIdx.x % 6;
    int wg   = blockIdx.x / 6;
    int wi   = wg & 63;
    int wh   = wi >> 3, ww = wi & 7;
    int tid  = threadIdx.x;
    int lane = tid & 31, wid = tid >> 5;
    int g = lane >> 2, t = lane & 3;

    // load + convert q/k/v
    size_t base = (size_t)wg * 49 * 576 + head * 32;
    for (int idx = tid; idx < 49 * 32; idx += 128) {
        int n = idx >> 5, dd = idx & 31;
        size_t o = base + (size_t)n * 576 + dd;
        sq[n][dd] = f2tf(g_qkv[o]);
        sk[n][dd] = f2tf(g_qkv[o + 192]);
        sv[n][dd] = f2tf(g_qkv[o + 384]);
    }
    for (int idx = tid; idx < 15 * 32; idx += 128) sq[49 + (idx >> 5)][idx & 31] = 0u;
    for (int idx = tid; idx < 7 * 32; idx += 128) {
        sk[49 + (idx >> 5)][idx & 31] = 0u;
        sv[49 + (idx >> 5)][idx & 31] = 0u;
    }
    __syncthreads();

    // ---- scores = Q K^T : M=64(pad), N=56(pad), K=32. warp wid -> m-tile.
    float sc[7][4] = {};
    #pragma unroll
    for (int ks = 0; ks < 4; ks++) {
        unsigned a[4];
        int r = wid * 16 + g, c = ks * 8 + t;
        a[0] = sq[r][c];     a[1] = sq[r + 8][c];
        a[2] = sq[r][c + 4]; a[3] = sq[r + 8][c + 4];
        #pragma unroll
        for (int ni = 0; ni < 7; ni++) {
            unsigned b[2];
            int m = ni * 8 + g;
            b[0] = sk[m][ks * 8 + t];
            b[1] = sk[m][ks * 8 + t + 4];
            mma8(sc[ni], a, b);
        }
    }

    // bias + mask + scale, write to sp
    const float scale = 0.17677669529663687f;
    bool edge_h = (wh == 7), edge_w = (ww == 7);
    #pragma unroll
    for (int ni = 0; ni < 7; ni++) {
        #pragma unroll
        for (int j = 0; j < 4; j++) {
            int row = wid * 16 + g + ((j >= 2) ? 8 : 0);
            int col = ni * 8 + 2 * t + (j & 1);
            float v = 0.f;
            if (row < 49 && col < 49) {
                int i1 = row / 7, j1 = row - i1 * 7;
                int i2 = col / 7, j2 = col - i2 * 7;
                float bias = rpb[((i1 - i2 + 6) * 13 + (j1 - j2 + 6)) * 6 + head];
                int rn = (edge_h ? ((i1 < 4) ? 1 : 2) : 0) * 3 + (edge_w ? ((j1 < 4) ? 1 : 2) : 0);
                int rm = (edge_h ? ((i2 < 4) ? 1 : 2) : 0) * 3 + (edge_w ? ((j2 < 4) ? 1 : 2) : 0);
                if (rn != rm) bias -= 100.f;
                v = sc[ni][j] * scale + bias;
            }
            sp[row][col] = v;
        }
    }
    __syncthreads();

    // softmax over cols [0,49) for rows [0,49); probs stored tf32-rounded.
    if (tid < 49) {
        float mx = -1e30f;
        #pragma unroll 7
        for (int m = 0; m < 49; m++) mx = fmaxf(mx, sp[tid][m]);
        float sum = 0.f;
        float e49[49];
        #pragma unroll 7
        for (int m = 0; m < 49; m++) { float e = expf(sp[tid][m] - mx); e49[m] = e; sum += e; }
        float inv = 1.f / sum;
        #pragma unroll 7
        for (int m = 0; m < 49; m++) sp[tid][m] = __uint_as_float(f2tf(e49[m] * inv));
        // cols 49..55 stay 0 from the score phase
    }
    __syncthreads();

    // ---- out = P V : M=64(pad), N=32, K=56. warp wid -> m-tile.
    float dv[4][4] = {};
    #pragma unroll
    for (int ks = 0; ks < 7; ks++) {
        unsigned a[4];
        int r = wid * 16 + g, c = ks * 8 + t;
        a[0] = __float_as_uint(sp[r][c]);     a[1] = __float_as_uint(sp[r + 8][c]);
        a[2] = __float_as_uint(sp[r][c + 4]); a[3] = __float_as_uint(sp[r + 8][c + 4]);
        #pragma unroll
        for (int ni = 0; ni < 4; ni++) {
            unsigned b[2];
            b[0] = sv[ks * 8 + t][ni * 8 + g];
            b[1] = sv[ks * 8 + t + 4][ni * 8 + g];
            mma8(dv[ni], a, b);
        }
    }
    #pragma unroll
    for (int ni = 0; ni < 4; ni++) {
        #pragma unroll
        for (int j = 0; j < 4; j += 2) {
            int row = wid * 16 + g + ((j >= 2) ? 8 : 0);
            if (row < 49) {
                int col = ni * 8 + 2 * t;
                float2 o = { dv[ni][j], dv[ni][j + 1] };
                *(float2*)(g_att + (size_t)(wg * 49 + row) * CDIM + head * 32 + col) = o;
            }
        }
    }
}

// ---------------------------------------------------------------------------
// Proj: y[perm(t)] = x[perm(t)] + g_att[t] @ proj_w + proj_b  (N=192, K=192)
// ---------------------------------------------------------------------------
__global__ __launch_bounds__(256) void gemm_proj_t(
    const float* __restrict__ x, const float* __restrict__ w,
    const float* __restrict__ wb, float* __restrict__ out)
{
    __shared__ unsigned As[128][36];
    __shared__ unsigned Bs[32][72];
    __shared__ int rP[128];
    int tid = threadIdx.x;
    int lane = tid & 31, wid = tid >> 5;
    int g = lane >> 2, t = lane & 3;
    int wm = (wid >> 1) * 32, wn = (wid & 1) * 32;
    int m0 = blockIdx.x << 7, n0 = blockIdx.y << 6;
    if (tid < 128) rP[tid] = perm_pixel(m0 + tid);
    __syncthreads();
    float d[2][4][4] = {};
    for (int kt = 0; kt < 192; kt += 32) {
        #pragma unroll
        for (int e = 0; e < 4; e++) {
            int idx = tid + e * 256;
            int r = idx >> 3, c = (idx & 7) << 2;
            float4 av = *(const float4*)(g_att + (size_t)(m0 + r) * CDIM + kt + c);
            uint4 u = { f2tf(av.x), f2tf(av.y), f2tf(av.z), f2tf(av.w) };
            *(uint4*)&As[r][c] = u;
        }
        #pragma unroll
        for (int e = 0; e < 2; e++) {
            int idx = tid + e * 256;
            int r = idx >> 4, c = (idx & 15) << 2;
            float4 wv = *(const float4*)(w + (size_t)(kt + r) * CDIM + n0 + c);
            uint4 u = { f2tf(wv.x), f2tf(wv.y), f2tf(wv.z), f2tf(wv.w) };
            *(uint4*)&Bs[r][c] = u;
        }
        __syncthreads();
        mma_tile(As, Bs, d, wm, wn, g, t);
        __syncthreads();
    }
    #pragma unroll
    for (int mi = 0; mi < 2; mi++)
        #pragma unroll
        for (int ni = 0; ni < 4; ni++) {
            int rl = wm + mi * 16 + g;
            int col = n0 + wn + ni * 8 + 2 * t;
            float2 b2 = *(const float2*)(wb + col);
            #pragma unroll
            for (int h = 0; h < 2; h++) {
                int p = rP[rl + 8 * h];
                float2 sc2 = *(const float2*)(x + (size_t)p * CDIM + col);
                float2 o = { d[mi][ni][2 * h] + b2.x + sc2.x,
                             d[mi][ni][2 * h + 1] + b2.y + sc2.y };
                *(float2*)(out + (size_t)p * CDIM + col) = o;
            }
        }
}

// ---------------------------------------------------------------------------
// FC1: g_h[t] = gelu( LN2(y[t]) @ fc1_w + fc1_b )  (N=768, K=192)
// ---------------------------------------------------------------------------
__global__ __launch_bounds__(256) void gemm_fc1_t(
    const float* __restrict__ y, const float* __restrict__ w,
    const float* __restrict__ wb, const float* __restrict__ gg,
    const float* __restrict__ bb)
{
    __shared__ unsigned As[128][36];
    __shared__ unsigned Bs[32][72];
    __shared__ float rM[128], rR[128];
    int tid = threadIdx.x;
    int lane = tid & 31, wid = tid >> 5;
    int g = lane >> 2, t = lane & 3;
    int wm = (wid >> 1) * 32, wn = (wid & 1) * 32;
    int m0 = blockIdx.x << 7, n0 = blockIdx.y << 6;
    if (tid < 128) { rM[tid] = g_mu2[m0 + tid]; rR[tid] = g_rs2[m0 + tid]; }
    __syncthreads();
    float d[2][4][4] = {};
    for (int kt = 0; kt < 192; kt += 32) {
        #pragma unroll
        for (int e = 0; e < 4; e++) {
            int idx = tid + e * 256;
            int r = idx >> 3, c = (idx & 7) << 2;
            int gk = kt + c;
            float4 xv = *(const float4*)(y + (size_t)(m0 + r) * CDIM + gk);
            float4 gv = *(const float4*)(gg + gk);
            float4 bv = *(const float4*)(bb + gk);
            float mm = rM[r], rr = rR[r];
            uint4 u;
            u.x = f2tf((xv.x - mm) * rr * gv.x + bv.x);
            u.y = f2tf((xv.y - mm) * rr * gv.y + bv.y);
            u.z = f2tf((xv.z - mm) * rr * gv.z + bv.z);
            u.w = f2tf((xv.w - mm) * rr * gv.w + bv.w);
            *(uint4*)&As[r][c] = u;
        }
        #pragma unroll
        for (int e = 0; e < 2; e++) {
            int idx = tid + e * 256;
            int r = idx >> 4, c = (idx & 15) << 2;
            float4 wv = *(const float4*)(w + (size_t)(kt + r) * 768 + n0 + c);
            uint4 u = { f2tf(wv.x), f2tf(wv.y), f2tf(wv.z), f2tf(wv.w) };
            *(uint4*)&Bs[r][c] = u;
        }
        __syncthreads();
        mma_tile(As, Bs, d, wm, wn, g, t);
        __syncthreads();
    }
    const float iS2 = 0.70710678118654752f;
    #pragma unroll
    for (int mi = 0; mi < 2; mi++)
        #pragma unroll
        for (int ni = 0; ni < 4; ni++) {
            int row = m0 + wm + mi * 16 + g;
            int col = n0 + wn + ni * 8 + 2 * t;
            float2 b2 = *(const float2*)(wb + col);
            float v0 = d[mi][ni][0] + b2.x, v1 = d[mi][ni][1] + b2.y;
            float v2 = d[mi][ni][2] + b2.x, v3 = d[mi][ni][3] + b2.y;
            float2 o0 = { 0.5f * v0 * (1.f + erff(v0 * iS2)),
                          0.5f * v1 * (1.f + erff(v1 * iS2)) };
            float2 o1 = { 0.5f * v2 * (1.f + erff(v2 * iS2)),
                          0.5f * v3 * (1.f + erff(v3 * iS2)) };
            *(float2*)(g_h + (size_t)row * 768 + col) = o0;
            *(float2*)(g_h + (size_t)(row + 8) * 768 + col) = o1;
        }
}

// ---------------------------------------------------------------------------
// FC2: out[t] += g_h[t] @ fc2_w + fc2_b   (N=192, K=768), in-place
// ---------------------------------------------------------------------------
__global__ __launch_bounds__(256) void gemm_fc2_t(
    const float* __restrict__ w, const float* __restrict__ wb,
    float* __restrict__ out)
{
    __shared__ unsigned As[128][36];
    __shared__ unsigned Bs[32][72];
    int tid = threadIdx.x;
    int lane = tid & 31, wid = tid >> 5;
    int g = lane >> 2, t = lane & 3;
    int wm = (wid >> 1) * 32, wn = (wid & 1) * 32;
    int m0 = blockIdx.x << 7, n0 = blockIdx.y << 6;
    float d[2][4][4] = {};
    for (int kt = 0; kt < 768; kt += 32) {
        #pragma unroll
        for (int e = 0; e < 4; e++) {
            int idx = tid + e * 256;
            int r = idx >> 3, c = (idx & 7) << 2;
            float4 hv = *(const float4*)(g_h + (size_t)(m0 + r) * 768 + kt + c);
            uint4 u = { f2tf(hv.x), f2tf(hv.y), f2tf(hv.z), f2tf(hv.w) };
            *(uint4*)&As[r][c] = u;
        }
        #pragma unroll
        for (int e = 0; e < 2; e++) {
            int idx = tid + e * 256;
            int r = idx >> 4, c = (idx & 15) << 2;
            float4 wv = *(const float4*)(w + (size_t)(kt + r) * CDIM + n0 + c);
            uint4 u = { f2tf(wv.x), f2tf(wv.y), f2tf(wv.z), f2tf(wv.w) };
            *(uint4*)&Bs[r][c] = u;
        }
        __syncthreads();
        mma_tile(As, Bs, d, wm, wn, g, t);
        __syncthreads();
    }
    #pragma unroll
    for (int mi = 0; mi < 2; mi++)
        #pragma unroll
        for (int ni = 0; ni < 4; ni++) {
            int row = m0 + wm + mi * 16 + g;
            int col = n0 + wn + ni * 8 + 2 * t;
            float2 b2 = *(const float2*)(wb + col);
            float2 y0 = *(const float2*)(out + (size_t)row * CDIM + col);
            float2 y1 = *(const float2*)(out + (size_t)(row + 8) * CDIM + col);
            float2 o0 = { y0.x + d[mi][ni][0] + b2.x, y0.y + d[mi][ni][1] + b2.y };
            float2 o1 = { y1.x + d[mi][ni][2] + b2.x, y1.y + d[mi][ni][3] + b2.y };
            *(float2*)(out + (size_t)row * CDIM + col) = o0;
            *(float2*)(out + (size_t)(row + 8) * CDIM + col) = o1;
        }
}

// ---------------------------------------------------------------------------
extern "C" void kernel_launch(void* const* d_in, const int* in_sizes, int n_in,
                              void* d_out, int out_size) {
    const float* x      = (const float*)d_in[0];
    const float* n1g    = (const float*)d_in[1];
    const float* n1b    = (const float*)d_in[2];
    const float* qkv_w  = (const float*)d_in[3];
    const float* qkv_b  = (const float*)d_in[4];
    const float* rpb    = (const float*)d_in[5];
    const float* proj_w = (const float*)d_in[6];
    const float* proj_b = (const float*)d_in[7];
    const float* n2g    = (const float*)d_in[8];
    const float* n2b    = (const float*)d_in[9];
    const float* fc1_w  = (const float*)d_in[10];
    const float* fc1_b  = (const float*)d_in[11];
    const float* fc2_w  = (const float*)d_in[12];
    const float* fc2_b  = (const float*)d_in[13];
    float* out = (float*)d_out;

    ln_stats<<<TOKENS / 8, 256>>>(x, 0);
    gemm_qkv_t<<<dim3(784, 9), 256>>>(x, qkv_w, qkv_b, n1g, n1b);
    attn_t<<<12288, 128>>>(rpb);
    gemm_proj_t<<<dim3(784, 3), 256>>>(x, proj_w, proj_b, out);
    ln_stats<<<TOKENS / 8, 256>>>(out, 1);
    gemm_fc1_t<<<dim3(784, 12), 256>>>(out, fc1_w, fc1_b, n2g, n2b);
    gemm_fc2_t<<<dim3(784, 3), 256>>>(fc2_w, fc2_b, out);
}